// round 3
// baseline (speedup 1.0000x reference)
#include <cuda_runtime.h>
#include <math.h>

// ---------------- problem constants ----------------
#define B_      128
#define STREAM_ 512
#define INCH    4
#define EXTRA_  5
#define G_      2
#define STEP_   16
#define C_      10          // INCH + 1 + EXTRA
#define SIGC    1110        // C + C^2 + C^3
#define W_      31          // windows
#define F_      2220        // GROUPS * SIGC
#define RNN_    256
#define OUT_    10
#define KPAD    2224        // F_ padded to multiple of 16 for guard-free GEMM
#define MROWS   (W_ * B_)   // 3968
#define NGI     768         // 3 * RNN

// ---------------- device scratch (static, allowed) ----------------
__device__ float g_sig[MROWS * KPAD];     // ~35 MB
__device__ float g_Wp [NGI * KPAD];       // padded W_ih copy ~6.8 MB
__device__ float g_gi [MROWS * NGI];      // ~12 MB
__device__ float g_h  [2][B_ * RNN_];     // ping-pong hidden state

// =====================================================================
// Kernel 1: path signatures (Chen, depth 3).
// grid (31, 256): blockIdx.x = window w, blockIdx.y = b*2+g. 128 threads.
// Threads t<100 own (a,b)=(t/10,t%10): S2[a,b] scalar + S3[a,b,:] (10 regs),
// plus a private copy of S1[a]. No barriers in the step loop.
// =====================================================================
__global__ __launch_bounds__(128) void sig_kernel(
    const float* __restrict__ x,       // (128,512,4)
    const float* __restrict__ W_aug)   // (2,5,4)
{
    const int w  = blockIdx.x;
    const int bg = blockIdx.y;
    const int b  = bg >> 1;
    const int g  = bg & 1;
    const int tid = threadIdx.x;

    __shared__ __align__(16) float xs[32][4];
    __shared__ __align__(16) float dxw[31][10];

    // load 32-row x window
    {
        int row = tid >> 2, ch = tid & 3;
        xs[row][ch] = x[(b * STREAM_ + w * STEP_ + row) * INCH + ch];
    }
    __syncthreads();

    // build per-step increments dxw[j][c], c = [x(4), t(1), aug(5)]
    for (int idx = tid; idx < 31 * 10; idx += 128) {
        int j = idx / 10, c = idx % 10;
        float v;
        if (c < 4) {
            v = xs[j + 1][c] - xs[j][c];
        } else if (c == 4) {
            v = 1.0f / 511.0f;                       // linspace(0,1,512) increment
        } else {
            int e = c - 5;
            const float* wa = W_aug + (g * EXTRA_ + e) * INCH;
            v = 0.f;
            #pragma unroll
            for (int i = 0; i < 4; i++) v += wa[i] * (xs[j + 1][i] - xs[j][i]);
        }
        dxw[j][c] = v;
    }
    __syncthreads();

    const size_t base = (size_t)(w * B_ + b) * KPAD + (size_t)g * SIGC;

    if (tid < 100) {
        const int a  = tid / 10;
        const int bb = tid % 10;
        float s1a = 0.f, s2 = 0.f;
        float s3[10];
        #pragma unroll
        for (int c = 0; c < 10; c++) s3[c] = 0.f;

        for (int j = 0; j < 31; j++) {
            float dxa = dxw[j][a];
            float dxb = dxw[j][bb];
            // S3 uses OLD S2, S1:  S3 += (S2 + S1a*dxb/2 + dxa*dxb/6) * dx[c]
            float factor = s2 + dxb * (0.5f * s1a + (1.0f / 6.0f) * dxa);
            #pragma unroll
            for (int c = 0; c < 10; c++) s3[c] += factor * dxw[j][c];
            // S2 uses OLD S1:      S2 += S1a*dxb + dxa*dxb/2
            s2  += dxb * (s1a + 0.5f * dxa);
            s1a += dxa;
        }
        if (bb == 0) g_sig[base + a] = s1a;                 // S1 block (10)
        g_sig[base + 10 + tid] = s2;                        // S2 block (100)
        #pragma unroll
        for (int c = 0; c < 10; c++)                        // S3 block (1000)
            g_sig[base + 110 + tid * 10 + c] = s3[c];
    }
    // zero K-pad columns (once per row; let the g==1 block do it)
    if (g == 1 && tid < (KPAD - F_))
        g_sig[(size_t)(w * B_ + b) * KPAD + F_ + tid] = 0.f;
}

// =====================================================================
// Kernel 2: pad W_ih (768 x 2220) into g_Wp (768 x 2224), zero pad cols
// =====================================================================
__global__ __launch_bounds__(256) void prep_w(const float* __restrict__ Wih)
{
    int idx = blockIdx.x * 256 + threadIdx.x;
    if (idx < NGI * KPAD) {
        int n = idx / KPAD, k = idx - n * KPAD;
        g_Wp[idx] = (k < F_) ? Wih[n * F_ + k] : 0.f;
    }
}

// =====================================================================
// Kernel 3: GI = sig @ W_ih^T + b_ih   (M=3968, N=768, K=2224 padded)
// Classic SIMT SGEMM: 128x128 tile, BK=8, 256 threads, 8x8 microtile.
// =====================================================================
__global__ __launch_bounds__(256) void gemm_gi(const float* __restrict__ bih)
{
    __shared__ __align__(16) float As[8][128];
    __shared__ __align__(16) float Bs[8][128];

    const int m0 = blockIdx.x * 128;
    const int n0 = blockIdx.y * 128;
    const int tid = threadIdx.x;
    const int tx = tid & 15;   // n sub-tile
    const int ty = tid >> 4;   // m sub-tile

    const int lrow = tid >> 1;          // 0..127
    const int lk   = (tid & 1) * 4;     // 0 or 4

    float acc[8][8];
    #pragma unroll
    for (int i = 0; i < 8; i++)
        #pragma unroll
        for (int j = 0; j < 8; j++) acc[i][j] = 0.f;

    const float* Aptr = g_sig + (size_t)(m0 + lrow) * KPAD + lk;
    const float* Bptr = g_Wp  + (size_t)(n0 + lrow) * KPAD + lk;

    for (int k0 = 0; k0 < KPAD; k0 += 8) {
        float4 va = *(const float4*)(Aptr + k0);
        float4 vb = *(const float4*)(Bptr + k0);
        As[lk + 0][lrow] = va.x; As[lk + 1][lrow] = va.y;
        As[lk + 2][lrow] = va.z; As[lk + 3][lrow] = va.w;
        Bs[lk + 0][lrow] = vb.x; Bs[lk + 1][lrow] = vb.y;
        Bs[lk + 2][lrow] = vb.z; Bs[lk + 3][lrow] = vb.w;
        __syncthreads();

        #pragma unroll
        for (int kk = 0; kk < 8; kk++) {
            float4 a0 = *(const float4*)&As[kk][ty * 8];
            float4 a1 = *(const float4*)&As[kk][ty * 8 + 4];
            float4 b0 = *(const float4*)&Bs[kk][tx * 8];
            float4 b1 = *(const float4*)&Bs[kk][tx * 8 + 4];
            float a[8] = {a0.x, a0.y, a0.z, a0.w, a1.x, a1.y, a1.z, a1.w};
            float bv[8] = {b0.x, b0.y, b0.z, b0.w, b1.x, b1.y, b1.z, b1.w};
            #pragma unroll
            for (int i = 0; i < 8; i++)
                #pragma unroll
                for (int j = 0; j < 8; j++) acc[i][j] += a[i] * bv[j];
        }
        __syncthreads();
    }

    // epilogue: add bias, write GI
    float bias[8];
    #pragma unroll
    for (int j = 0; j < 8; j++) bias[j] = bih[n0 + tx * 8 + j];
    #pragma unroll
    for (int i = 0; i < 8; i++) {
        int m = m0 + ty * 8 + i;
        float* dst = g_gi + (size_t)m * NGI + n0 + tx * 8;
        float4 o0, o1;
        o0.x = acc[i][0] + bias[0]; o0.y = acc[i][1] + bias[1];
        o0.z = acc[i][2] + bias[2]; o0.w = acc[i][3] + bias[3];
        o1.x = acc[i][4] + bias[4]; o1.y = acc[i][5] + bias[5];
        o1.z = acc[i][6] + bias[6]; o1.w = acc[i][7] + bias[7];
        *(float4*)(dst)     = o0;
        *(float4*)(dst + 4) = o1;
    }
}

// =====================================================================
// Kernel 4: zero h0
// =====================================================================
__global__ void zero_h()
{
    int i = blockIdx.x * 256 + threadIdx.x;
    if (i < B_ * RNN_) g_h[0][i] = 0.f;
}

// =====================================================================
// Kernel 5: one fused GRU step: gh = h @ W_hh^T + b_hh, gates, new h.
// grid (4, 16): 32-batch tile x 16-gate tile. 256 threads.
// Thread (tx=j-local, ty=b-local) computes 2 batch rows x 1 gate col,
// all 3 gates (r,z,n) in registers.
// =====================================================================
__global__ __launch_bounds__(256) void gru_step(
    int t,
    const float* __restrict__ Whh,   // (768,256)
    const float* __restrict__ bhh)   // (768)
{
    const float* __restrict__ h_in  = g_h[t & 1];
    float*       __restrict__ h_out = g_h[(t + 1) & 1];
    const float* __restrict__ gi_t  = g_gi + (size_t)t * B_ * NGI;

    const int b0 = blockIdx.x * 32;
    const int j0 = blockIdx.y * 16;
    const int tid = threadIdx.x;
    const int tx = tid & 15;   // gate column local
    const int ty = tid >> 4;   // batch local (handles ty and ty+16)

    __shared__ __align__(16) float hs[32][68];
    __shared__ __align__(16) float ws[3][16][68];

    float acc[3][2] = {{0.f, 0.f}, {0.f, 0.f}, {0.f, 0.f}};

    for (int kc = 0; kc < RNN_; kc += 64) {
        for (int i = tid; i < 32 * 16; i += 256) {
            int r = i >> 4, c4 = (i & 15) * 4;
            float4 v = *(const float4*)&h_in[(b0 + r) * RNN_ + kc + c4];
            *(float4*)&hs[r][c4] = v;
        }
        for (int i = tid; i < 48 * 16; i += 256) {
            int r = i >> 4, c4 = (i & 15) * 4;
            int gg = r >> 4, j = r & 15;
            float4 v = *(const float4*)&Whh[(gg * RNN_ + j0 + j) * RNN_ + kc + c4];
            *(float4*)&ws[gg][j][c4] = v;
        }
        __syncthreads();

        #pragma unroll
        for (int k = 0; k < 64; k += 4) {
            float4 h0 = *(const float4*)&hs[ty][k];
            float4 h1 = *(const float4*)&hs[ty + 16][k];
            #pragma unroll
            for (int gg = 0; gg < 3; gg++) {
                float4 wv = *(const float4*)&ws[gg][tx][k];
                acc[gg][0] += wv.x * h0.x + wv.y * h0.y + wv.z * h0.z + wv.w * h0.w;
                acc[gg][1] += wv.x * h1.x + wv.y * h1.y + wv.z * h1.z + wv.w * h1.w;
            }
        }
        __syncthreads();
    }

    const int j = j0 + tx;
    const float br = bhh[j], bz = bhh[RNN_ + j], bn = bhh[2 * RNN_ + j];

    #pragma unroll
    for (int p = 0; p < 2; p++) {
        const int b = b0 + ty + p * 16;
        float hr = acc[0][p] + br;
        float hz = acc[1][p] + bz;
        float hn = acc[2][p] + bn;
        float ir  = gi_t[b * NGI + j];
        float iz  = gi_t[b * NGI + RNN_ + j];
        float inn = gi_t[b * NGI + 2 * RNN_ + j];
        float r = 1.f / (1.f + expf(-(ir + hr)));
        float z = 1.f / (1.f + expf(-(iz + hz)));
        float n = tanhf(inn + r * hn);
        float hprev = h_in[b * RNN_ + j];
        h_out[b * RNN_ + j] = (1.f - z) * n + z * hprev;
    }
}

// =====================================================================
// Kernel 6: output head: sigmoid(h @ W_out^T + b_out). Warp per output.
// =====================================================================
__global__ __launch_bounds__(256) void out_kernel(
    const float* __restrict__ Wout,  // (10,256)
    const float* __restrict__ bout,  // (10)
    float* __restrict__ out)         // (128,10)
{
    const float* __restrict__ h = g_h[1];  // final h after 31 steps (odd)
    int warp = (blockIdx.x * blockDim.x + threadIdx.x) >> 5;
    int lane = threadIdx.x & 31;
    if (warp >= B_ * OUT_) return;
    int b = warp / OUT_, o = warp - b * OUT_;
    float s = 0.f;
    for (int k = lane; k < RNN_; k += 32) s += h[b * RNN_ + k] * Wout[o * RNN_ + k];
    #pragma unroll
    for (int off = 16; off; off >>= 1) s += __shfl_down_sync(0xffffffffu, s, off);
    if (lane == 0) out[b * OUT_ + o] = 1.f / (1.f + expf(-(s + bout[o])));
}

// =====================================================================
extern "C" void kernel_launch(void* const* d_in, const int* in_sizes, int n_in,
                              void* d_out, int out_size)
{
    const float* x     = (const float*)d_in[0];
    const float* W_aug = (const float*)d_in[1];
    // d_in[2] = b_aug: cancels in increments, unused
    const float* W_ih  = (const float*)d_in[3];
    const float* W_hh  = (const float*)d_in[4];
    const float* b_ih  = (const float*)d_in[5];
    const float* b_hh  = (const float*)d_in[6];
    const float* W_out = (const float*)d_in[7];
    const float* b_out = (const float*)d_in[8];
    float* out = (float*)d_out;

    sig_kernel<<<dim3(W_, B_ * G_), 128>>>(x, W_aug);
    prep_w<<<(NGI * KPAD + 255) / 256, 256>>>(W_ih);
    gemm_gi<<<dim3(MROWS / 128, NGI / 128), 256>>>(b_ih);
    zero_h<<<(B_ * RNN_ + 255) / 256, 256>>>();
    for (int t = 0; t < W_; t++)
        gru_step<<<dim3(4, 16), 256>>>(t, W_hh, b_hh);
    out_kernel<<<(B_ * OUT_ * 32 + 255) / 256, 256>>>(W_out, b_out, out);
}

// round 5
// speedup vs baseline: 2.1125x; 2.1125x over previous
#include <cuda_runtime.h>
#include <cuda_bf16.h>
#include <math.h>
#include <stdint.h>

// ---------------- problem constants ----------------
#define B_      128
#define STREAM_ 512
#define INCH    4
#define EXTRA_  5
#define G_      2
#define STEP_   16
#define SIGC    1110        // C + C^2 + C^3, C=10
#define W_      31          // windows
#define F_      2220        // GROUPS * SIGC
#define RNN_    256
#define OUT_    10
#define KP2     2240        // F_ padded to multiple of 64 (bf16 chunk)
#define MROWS   (W_ * B_)   // 3968
#define NGI     768         // 3 * RNN
#define NC      (KP2 / 64)  // 35 K-chunks of 64 bf16 (128 bytes)

// ---------------- device scratch (static, allowed) ----------------
__device__ __nv_bfloat16 g_A0[MROWS * KP2];   // sig hi  (~17.8 MB)
__device__ __nv_bfloat16 g_A1[MROWS * KP2];   // sig lo
__device__ __nv_bfloat16 g_B0[NGI * KP2];     // W_ih hi (~3.4 MB)
__device__ __nv_bfloat16 g_B1[NGI * KP2];     // W_ih lo
__device__ float g_gi[MROWS * NGI];           // ~12 MB
__device__ float g_h [2][B_ * RNN_];          // ping-pong hidden state

// ---------------- PTX helpers (portable: sm_80/90 class only) ----------------
__device__ __forceinline__ uint32_t smem_u32(const void* p) {
    uint32_t a;
    asm("{ .reg .u64 t; cvta.to.shared.u64 t, %1; cvt.u32.u64 %0, t; }" : "=r"(a) : "l"(p));
    return a;
}

__device__ __forceinline__ uint32_t swz(uint32_t off) { return off ^ ((off >> 3) & 0x70); }

#define LDSM4(r0, r1, r2, r3, addr)                                               \
    asm volatile("ldmatrix.sync.aligned.m8n8.x4.shared.b16 {%0,%1,%2,%3}, [%4];"  \
        : "=r"(r0), "=r"(r1), "=r"(r2), "=r"(r3) : "r"(addr))

// D += A(16x16) * B(16x8), bf16 in, fp32 accum. row.col = both K-contiguous.
#define MMA16816(d, a, b0v, b1v)                                                  \
    asm volatile("mma.sync.aligned.m16n8k16.row.col.f32.bf16.bf16.f32 "           \
        "{%0,%1,%2,%3}, {%4,%5,%6,%7}, {%8,%9}, {%0,%1,%2,%3};"                   \
        : "+f"((d)[0]), "+f"((d)[1]), "+f"((d)[2]), "+f"((d)[3])                  \
        : "r"((a)[0]), "r"((a)[1]), "r"((a)[2]), "r"((a)[3]), "r"(b0v), "r"(b1v))

// split fp32 -> two bf16 (hi = rn(v), lo = rn(v - hi))
__device__ __forceinline__ void store_split(size_t idx, float v,
                                            __nv_bfloat16* a0, __nv_bfloat16* a1) {
    __nv_bfloat16 h = __float2bfloat16(v);
    a0[idx] = h;
    a1[idx] = __float2bfloat16(v - __bfloat162float(h));
}

// =====================================================================
// Kernel 1: path signatures (Chen, depth 3) -> split bf16 into g_A0/g_A1
// =====================================================================
__global__ __launch_bounds__(128) void sig_kernel(
    const float* __restrict__ x,       // (128,512,4)
    const float* __restrict__ W_aug)   // (2,5,4)
{
    const int w  = blockIdx.x;
    const int bg = blockIdx.y;
    const int b  = bg >> 1;
    const int g  = bg & 1;
    const int tid = threadIdx.x;

    __shared__ __align__(16) float xs[32][4];
    __shared__ __align__(16) float dxw[31][10];

    {
        int row = tid >> 2, ch = tid & 3;
        xs[row][ch] = x[(b * STREAM_ + w * STEP_ + row) * INCH + ch];
    }
    __syncthreads();

    for (int idx = tid; idx < 31 * 10; idx += 128) {
        int j = idx / 10, c = idx % 10;
        float v;
        if (c < 4) {
            v = xs[j + 1][c] - xs[j][c];
        } else if (c == 4) {
            v = 1.0f / 511.0f;
        } else {
            int e = c - 5;
            const float* wa = W_aug + (g * EXTRA_ + e) * INCH;
            v = 0.f;
            #pragma unroll
            for (int i = 0; i < 4; i++) v += wa[i] * (xs[j + 1][i] - xs[j][i]);
        }
        dxw[j][c] = v;
    }
    __syncthreads();

    const size_t base = (size_t)(w * B_ + b) * KP2 + (size_t)g * SIGC;

    if (tid < 100) {
        const int a  = tid / 10;
        const int bb = tid % 10;
        float s1a = 0.f, s2 = 0.f;
        float s3[10];
        #pragma unroll
        for (int c = 0; c < 10; c++) s3[c] = 0.f;

        for (int j = 0; j < 31; j++) {
            float dxa = dxw[j][a];
            float dxb = dxw[j][bb];
            float factor = s2 + dxb * (0.5f * s1a + (1.0f / 6.0f) * dxa);
            #pragma unroll
            for (int c = 0; c < 10; c++) s3[c] += factor * dxw[j][c];
            s2  += dxb * (s1a + 0.5f * dxa);
            s1a += dxa;
        }
        if (bb == 0) store_split(base + a, s1a, g_A0, g_A1);
        store_split(base + 10 + tid, s2, g_A0, g_A1);
        #pragma unroll
        for (int c = 0; c < 10; c++)
            store_split(base + 110 + tid * 10 + c, s3[c], g_A0, g_A1);
    }
    // zero K-pad columns (g==1 block handles it once per row)
    if (g == 1 && tid < (KP2 - F_)) {
        size_t idx = (size_t)(w * B_ + b) * KP2 + F_ + tid;
        g_A0[idx] = __float2bfloat16(0.f);
        g_A1[idx] = __float2bfloat16(0.f);
    }
}

// =====================================================================
// Kernel 2: split+pad W_ih (768 x 2220) into g_B0/g_B1 (768 x 2240)
// =====================================================================
__global__ __launch_bounds__(256) void prep_w(const float* __restrict__ Wih)
{
    int idx = blockIdx.x * 256 + threadIdx.x;
    if (idx < NGI * KP2) {
        int n = idx / KP2, k = idx - n * KP2;
        float v = (k < F_) ? Wih[n * F_ + k] : 0.f;
        store_split((size_t)idx, v, g_B0, g_B1);
    }
}

// =====================================================================
// Kernel 3: GI = sig @ W_ih^T + b_ih via mma.sync bf16-split (3 products).
// 128x128 CTA tile, 8 warps of 32(M)x64(N), K-chunk 64, double-buffered
// cp.async, SW128 smem, non-trans ldmatrix for both operands (TN layout).
// =====================================================================
#define TILE_B      16384                  // 128 rows x 128 bytes
#define STAGE_B     (4 * TILE_B)           // A0,A1,B0,B1 tiles
#define GEMM_SMEM   (2 * STAGE_B)          // 131072 bytes (2 stages)

__global__ __launch_bounds__(256, 1) void gemm_mma(const float* __restrict__ bih)
{
    extern __shared__ char smem[];
    const uint32_t sb = smem_u32(smem);
    const int tid  = threadIdx.x;
    const int lane = tid & 31;
    const int wid  = tid >> 5;
    const int wm   = wid >> 1;        // 0..3 -> M offset 32*wm
    const int wn   = wid & 1;         // 0..1 -> N offset 64*wn
    const int m0 = blockIdx.x * 128;
    const int n0 = blockIdx.y * 128;

    const __nv_bfloat16* gsrc[4] = {
        g_A0 + (size_t)m0 * KP2, g_A1 + (size_t)m0 * KP2,
        g_B0 + (size_t)n0 * KP2, g_B1 + (size_t)n0 * KP2
    };

    auto load_chunk = [&](int c) {
        uint32_t sbase = sb + (uint32_t)(c & 1) * STAGE_B;
        #pragma unroll
        for (int tt = 0; tt < 4; tt++) {
            const __nv_bfloat16* gp = gsrc[tt];
            #pragma unroll
            for (int it = 0; it < 4; it++) {
                int i = tid + it * 256;           // 0..1023
                int row = i >> 3, seg = i & 7;    // 128 rows x 8 16B-segs
                uint32_t dst = sbase + (uint32_t)tt * TILE_B
                             + swz((uint32_t)row * 128 + (uint32_t)seg * 16);
                const void* src = gp + (size_t)row * KP2 + (size_t)c * 64 + seg * 8;
                asm volatile("cp.async.cg.shared.global [%0], [%1], 16;\n"
                             :: "r"(dst), "l"(src));
            }
        }
        asm volatile("cp.async.commit_group;\n" ::: "memory");
    };

    // fp32 accumulators: [mtile(16)][ntile8][4]
    float acc[2][8][4];
    #pragma unroll
    for (int i = 0; i < 2; i++)
        #pragma unroll
        for (int j = 0; j < 8; j++)
            #pragma unroll
            for (int k = 0; k < 4; k++) acc[i][j][k] = 0.f;

    // ldmatrix per-lane address components.
    // A x4: reg0 = m(0-7)k(0-7), reg1 = m(8-15)k(0-7), reg2 = m(0-7)k(8-15),
    //       reg3 = m(8-15)k(8-15)  -> row = l&15, byte = (l>=16)*16
    const uint32_t a_row  = (uint32_t)(wm * 32 + (lane & 15));
    const uint32_t a_byte = (uint32_t)((lane >> 4) << 4);
    // B x4: reg0 = n(0-7)k(0-7), reg1 = n(0-7)k(8-15), reg2 = n(8-15)k(0-7),
    //       reg3 = n(8-15)k(8-15) -> row = (l&7) + (l>=16)*8, byte = (l&8)*2
    const uint32_t b_row  = (uint32_t)(wn * 64 + (lane & 7) + ((lane >> 4) << 3));
    const uint32_t b_byte = (uint32_t)((lane & 8) << 1);

    load_chunk(0);

    for (int c = 0; c < NC; c++) {
        if (c + 1 < NC) load_chunk(c + 1);
        if (c + 1 < NC) asm volatile("cp.async.wait_group 1;\n" ::: "memory");
        else            asm volatile("cp.async.wait_group 0;\n" ::: "memory");
        __syncthreads();

        const uint32_t stage = sb + (uint32_t)(c & 1) * STAGE_B;
        const uint32_t aB0 = stage;
        const uint32_t aB1 = stage + TILE_B;
        const uint32_t bB0 = stage + 2 * TILE_B;
        const uint32_t bB1 = stage + 3 * TILE_B;

        #pragma unroll
        for (int ks = 0; ks < 4; ks++) {
            const uint32_t kb = (uint32_t)ks * 32;
            uint32_t a0f[2][4], a1f[2][4];
            #pragma unroll
            for (int mt = 0; mt < 2; mt++) {
                uint32_t off = swz((a_row + mt * 16) * 128 + kb + a_byte);
                LDSM4(a0f[mt][0], a0f[mt][1], a0f[mt][2], a0f[mt][3], aB0 + off);
                LDSM4(a1f[mt][0], a1f[mt][1], a1f[mt][2], a1f[mt][3], aB1 + off);
            }
            uint32_t b0f[4][4], b1f[4][4];
            #pragma unroll
            for (int nt = 0; nt < 4; nt++) {
                uint32_t off = swz((b_row + nt * 16) * 128 + kb + b_byte);
                LDSM4(b0f[nt][0], b0f[nt][1], b0f[nt][2], b0f[nt][3], bB0 + off);
                LDSM4(b1f[nt][0], b1f[nt][1], b1f[nt][2], b1f[nt][3], bB1 + off);
            }
            #pragma unroll
            for (int mt = 0; mt < 2; mt++) {
                #pragma unroll
                for (int nt = 0; nt < 4; nt++) {
                    // product A0*B0
                    MMA16816(acc[mt][2 * nt],     a0f[mt], b0f[nt][0], b0f[nt][1]);
                    MMA16816(acc[mt][2 * nt + 1], a0f[mt], b0f[nt][2], b0f[nt][3]);
                    // product A0*B1
                    MMA16816(acc[mt][2 * nt],     a0f[mt], b1f[nt][0], b1f[nt][1]);
                    MMA16816(acc[mt][2 * nt + 1], a0f[mt], b1f[nt][2], b1f[nt][3]);
                    // product A1*B0
                    MMA16816(acc[mt][2 * nt],     a1f[mt], b0f[nt][0], b0f[nt][1]);
                    MMA16816(acc[mt][2 * nt + 1], a1f[mt], b0f[nt][2], b0f[nt][3]);
                }
            }
        }
        __syncthreads();
    }

    // epilogue: c fragment thread t holds rows {t/4, t/4+8}, cols {2(t%4), +1}
    float2 bias[8];
    {
        const int nbase = n0 + wn * 64 + 2 * (lane & 3);
        #pragma unroll
        for (int nt8 = 0; nt8 < 8; nt8++) {
            bias[nt8].x = bih[nbase + nt8 * 8];
            bias[nt8].y = bih[nbase + nt8 * 8 + 1];
        }
    }
    #pragma unroll
    for (int mt = 0; mt < 2; mt++) {
        const int mlo = m0 + wm * 32 + mt * 16 + (lane >> 2);
        #pragma unroll
        for (int nt8 = 0; nt8 < 8; nt8++) {
            const int n = n0 + wn * 64 + nt8 * 8 + 2 * (lane & 3);
            float2 lo, hi;
            lo.x = acc[mt][nt8][0] + bias[nt8].x;
            lo.y = acc[mt][nt8][1] + bias[nt8].y;
            hi.x = acc[mt][nt8][2] + bias[nt8].x;
            hi.y = acc[mt][nt8][3] + bias[nt8].y;
            *(float2*)(g_gi + (size_t)mlo * NGI + n)       = lo;
            *(float2*)(g_gi + (size_t)(mlo + 8) * NGI + n) = hi;
        }
    }
}

// =====================================================================
// Kernel 4: zero h0
// =====================================================================
__global__ void zero_h()
{
    int i = blockIdx.x * 256 + threadIdx.x;
    if (i < B_ * RNN_) g_h[0][i] = 0.f;
}

// =====================================================================
// Kernel 5: fused GRU step. grid (8,16): 16-batch x 16-gate tiles,
// 256 threads, 1 (batch,gate) pair per thread, all 3 gates in regs.
// =====================================================================
__global__ __launch_bounds__(256) void gru_step(
    int t,
    const float* __restrict__ Whh,   // (768,256)
    const float* __restrict__ bhh)   // (768)
{
    const float* __restrict__ h_in  = g_h[t & 1];
    float*       __restrict__ h_out = g_h[(t + 1) & 1];
    const float* __restrict__ gi_t  = g_gi + (size_t)t * B_ * NGI;

    const int b0 = blockIdx.x * 16;
    const int j0 = blockIdx.y * 16;
    const int tid = threadIdx.x;
    const int tx = tid & 15;   // gate column local
    const int ty = tid >> 4;   // batch row local

    __shared__ __align__(16) float hs[16][68];
    __shared__ __align__(16) float ws[3][16][68];

    float acc[3] = {0.f, 0.f, 0.f};

    for (int kc = 0; kc < RNN_; kc += 64) {
        {
            int r = tid >> 4, c4 = (tid & 15) * 4;
            float4 v = *(const float4*)&h_in[(b0 + r) * RNN_ + kc + c4];
            *(float4*)&hs[r][c4] = v;
        }
        #pragma unroll
        for (int it = 0; it < 3; it++) {
            int i = tid + it * 256;          // 0..767
            int r = i >> 4, c4 = (i & 15) * 4;
            int gg = r >> 4, j = r & 15;
            float4 v = *(const float4*)&Whh[(gg * RNN_ + j0 + j) * RNN_ + kc + c4];
            *(float4*)&ws[gg][j][c4] = v;
        }
        __syncthreads();

        #pragma unroll
        for (int k = 0; k < 64; k += 4) {
            float4 h4 = *(const float4*)&hs[ty][k];
            #pragma unroll
            for (int gg = 0; gg < 3; gg++) {
                float4 w4 = *(const float4*)&ws[gg][tx][k];
                acc[gg] += w4.x * h4.x + w4.y * h4.y + w4.z * h4.z + w4.w * h4.w;
            }
        }
        __syncthreads();
    }

    const int j = j0 + tx;
    const int b = b0 + ty;
    float hr = acc[0] + bhh[j];
    float hz = acc[1] + bhh[RNN_ + j];
    float hn = acc[2] + bhh[2 * RNN_ + j];
    float ir  = gi_t[b * NGI + j];
    float iz  = gi_t[b * NGI + RNN_ + j];
    float inn = gi_t[b * NGI + 2 * RNN_ + j];
    float r = 1.f / (1.f + expf(-(ir + hr)));
    float z = 1.f / (1.f + expf(-(iz + hz)));
    float n = tanhf(inn + r * hn);
    float hprev = h_in[b * RNN_ + j];
    h_out[b * RNN_ + j] = (1.f - z) * n + z * hprev;
}

// =====================================================================
// Kernel 6: output head: sigmoid(h @ W_out^T + b_out). Warp per output.
// =====================================================================
__global__ __launch_bounds__(256) void out_kernel(
    const float* __restrict__ Wout,  // (10,256)
    const float* __restrict__ bout,  // (10)
    float* __restrict__ out)         // (128,10)
{
    const float* __restrict__ h = g_h[1];  // final h after 31 steps
    int warp = (blockIdx.x * blockDim.x + threadIdx.x) >> 5;
    int lane = threadIdx.x & 31;
    if (warp >= B_ * OUT_) return;
    int b = warp / OUT_, o = warp - b * OUT_;
    float s = 0.f;
    for (int k = lane; k < RNN_; k += 32) s += h[b * RNN_ + k] * Wout[o * RNN_ + k];
    #pragma unroll
    for (int off = 16; off; off >>= 1) s += __shfl_down_sync(0xffffffffu, s, off);
    if (lane == 0) out[b * OUT_ + o] = 1.f / (1.f + expf(-(s + bout[o])));
}

// =====================================================================
extern "C" void kernel_launch(void* const* d_in, const int* in_sizes, int n_in,
                              void* d_out, int out_size)
{
    const float* x     = (const float*)d_in[0];
    const float* W_aug = (const float*)d_in[1];
    // d_in[2] = b_aug: constant, cancels in increments
    const float* W_ih  = (const float*)d_in[3];
    const float* W_hh  = (const float*)d_in[4];
    const float* b_ih  = (const float*)d_in[5];
    const float* b_hh  = (const float*)d_in[6];
    const float* W_out = (const float*)d_in[7];
    const float* b_out = (const float*)d_in[8];
    float* out = (float*)d_out;

    cudaFuncSetAttribute(gemm_mma, cudaFuncAttributeMaxDynamicSharedMemorySize, GEMM_SMEM);

    sig_kernel<<<dim3(W_, B_ * G_), 128>>>(x, W_aug);
    prep_w<<<(NGI * KP2 + 255) / 256, 256>>>(W_ih);
    gemm_mma<<<dim3(MROWS / 128, NGI / 128), 256, GEMM_SMEM>>>(b_ih);
    zero_h<<<(B_ * RNN_ + 255) / 256, 256>>>();
    for (int t = 0; t < W_; t++)
        gru_step<<<dim3(8, 16), 256>>>(t, W_hh, b_hh);
    out_kernel<<<(B_ * OUT_ * 32 + 255) / 256, 256>>>(W_out, b_out, out);
}

// round 6
// speedup vs baseline: 2.3761x; 1.1248x over previous
#include <cuda_runtime.h>
#include <cuda_bf16.h>
#include <math.h>
#include <stdint.h>

// ---------------- problem constants ----------------
#define B_      128
#define STREAM_ 512
#define INCH    4
#define EXTRA_  5
#define G_      2
#define STEP_   16
#define SIGC    1110        // C + C^2 + C^3, C=10
#define W_      31          // windows
#define F_      2220        // GROUPS * SIGC
#define RNN_    256
#define OUT_    10
#define KP2     2240        // F_ padded to multiple of 64 (bf16 chunk)
#define MROWS   (W_ * B_)   // 3968
#define NGI     768         // 3 * RNN
#define NC      (KP2 / 64)  // 35 K-chunks of 64 bf16 (128 bytes)

// ---------------- device scratch (static, allowed) ----------------
__device__ __nv_bfloat16 g_A0[MROWS * KP2];   // sig hi  (~17.8 MB)
__device__ __nv_bfloat16 g_A1[MROWS * KP2];   // sig lo
__device__ __nv_bfloat16 g_B0[NGI * KP2];     // W_ih hi (~3.4 MB)
__device__ __nv_bfloat16 g_B1[NGI * KP2];     // W_ih lo
__device__ float g_gi[MROWS * NGI];           // ~12 MB
__device__ float g_h [2][B_ * RNN_];          // ping-pong hidden state

// grid barrier state (self-resetting; gen monotonic across graph replays)
__device__ volatile unsigned g_bar_gen;
__device__ unsigned g_bar_cnt;

// ---------------- PTX helpers (portable: sm_80/90 class only) ----------------
__device__ __forceinline__ uint32_t smem_u32(const void* p) {
    uint32_t a;
    asm("{ .reg .u64 t; cvta.to.shared.u64 t, %1; cvt.u32.u64 %0, t; }" : "=r"(a) : "l"(p));
    return a;
}

__device__ __forceinline__ uint32_t swz(uint32_t off) { return off ^ ((off >> 3) & 0x70); }

#define LDSM4(r0, r1, r2, r3, addr)                                               \
    asm volatile("ldmatrix.sync.aligned.m8n8.x4.shared.b16 {%0,%1,%2,%3}, [%4];"  \
        : "=r"(r0), "=r"(r1), "=r"(r2), "=r"(r3) : "r"(addr))

// D += A(16x16) * B(16x8), bf16 in, fp32 accum. row.col = both K-contiguous.
#define MMA16816(d, a, b0v, b1v)                                                  \
    asm volatile("mma.sync.aligned.m16n8k16.row.col.f32.bf16.bf16.f32 "           \
        "{%0,%1,%2,%3}, {%4,%5,%6,%7}, {%8,%9}, {%0,%1,%2,%3};"                   \
        : "+f"((d)[0]), "+f"((d)[1]), "+f"((d)[2]), "+f"((d)[3])                  \
        : "r"((a)[0]), "r"((a)[1]), "r"((a)[2]), "r"((a)[3]), "r"(b0v), "r"(b1v))

// split fp32 -> two bf16 (hi = rn(v), lo = rn(v - hi))
__device__ __forceinline__ void store_split(size_t idx, float v,
                                            __nv_bfloat16* a0, __nv_bfloat16* a1) {
    __nv_bfloat16 h = __float2bfloat16(v);
    a0[idx] = h;
    a1[idx] = __float2bfloat16(v - __bfloat162float(h));
}

// =====================================================================
// Kernel 1: path signatures (Chen, depth 3) -> split bf16 into g_A0/g_A1
// =====================================================================
__global__ __launch_bounds__(128) void sig_kernel(
    const float* __restrict__ x,       // (128,512,4)
    const float* __restrict__ W_aug)   // (2,5,4)
{
    const int w  = blockIdx.x;
    const int bg = blockIdx.y;
    const int b  = bg >> 1;
    const int g  = bg & 1;
    const int tid = threadIdx.x;

    __shared__ __align__(16) float xs[32][4];
    __shared__ __align__(16) float dxw[31][10];

    {
        int row = tid >> 2, ch = tid & 3;
        xs[row][ch] = x[(b * STREAM_ + w * STEP_ + row) * INCH + ch];
    }
    __syncthreads();

    for (int idx = tid; idx < 31 * 10; idx += 128) {
        int j = idx / 10, c = idx % 10;
        float v;
        if (c < 4) {
            v = xs[j + 1][c] - xs[j][c];
        } else if (c == 4) {
            v = 1.0f / 511.0f;
        } else {
            int e = c - 5;
            const float* wa = W_aug + (g * EXTRA_ + e) * INCH;
            v = 0.f;
            #pragma unroll
            for (int i = 0; i < 4; i++) v += wa[i] * (xs[j + 1][i] - xs[j][i]);
        }
        dxw[j][c] = v;
    }
    __syncthreads();

    const size_t base = (size_t)(w * B_ + b) * KP2 + (size_t)g * SIGC;

    if (tid < 100) {
        const int a  = tid / 10;
        const int bb = tid % 10;
        float s1a = 0.f, s2 = 0.f;
        float s3[10];
        #pragma unroll
        for (int c = 0; c < 10; c++) s3[c] = 0.f;

        for (int j = 0; j < 31; j++) {
            float dxa = dxw[j][a];
            float dxb = dxw[j][bb];
            float factor = s2 + dxb * (0.5f * s1a + (1.0f / 6.0f) * dxa);
            #pragma unroll
            for (int c = 0; c < 10; c++) s3[c] += factor * dxw[j][c];
            s2  += dxb * (s1a + 0.5f * dxa);
            s1a += dxa;
        }
        if (bb == 0) store_split(base + a, s1a, g_A0, g_A1);
        store_split(base + 10 + tid, s2, g_A0, g_A1);
        #pragma unroll
        for (int c = 0; c < 10; c++)
            store_split(base + 110 + tid * 10 + c, s3[c], g_A0, g_A1);
    }
    // zero K-pad columns (g==1 block handles it once per row)
    if (g == 1 && tid < (KP2 - F_)) {
        size_t idx = (size_t)(w * B_ + b) * KP2 + F_ + tid;
        g_A0[idx] = __float2bfloat16(0.f);
        g_A1[idx] = __float2bfloat16(0.f);
    }
}

// =====================================================================
// Kernel 2: split+pad W_ih (768 x 2220) into g_B0/g_B1 (768 x 2240)
// =====================================================================
__global__ __launch_bounds__(256) void prep_w(const float* __restrict__ Wih)
{
    int idx = blockIdx.x * 256 + threadIdx.x;
    if (idx < NGI * KP2) {
        int n = idx / KP2, k = idx - n * KP2;
        float v = (k < F_) ? Wih[n * F_ + k] : 0.f;
        store_split((size_t)idx, v, g_B0, g_B1);
    }
}

// =====================================================================
// Kernel 3: GI = sig @ W_ih^T + b_ih via mma.sync bf16-split (3 products).
// 64x128 CTA tile (372 tiles, 2 CTAs/SM), 8 warps of 32(M)x32(N),
// K-chunk 64, double-buffered cp.async, SW128 smem, ldmatrix TN.
// =====================================================================
#define A_TILE_B    8192                   // 64 rows x 128 bytes
#define B_TILE_B    16384                  // 128 rows x 128 bytes
#define STAGE_B     (2 * A_TILE_B + 2 * B_TILE_B)   // 49152
#define GEMM_SMEM   (2 * STAGE_B)          // 98304 bytes (2 stages)

__global__ __launch_bounds__(256, 2) void gemm_mma(const float* __restrict__ bih)
{
    extern __shared__ char smem[];
    const uint32_t sb = smem_u32(smem);
    const int tid  = threadIdx.x;
    const int lane = tid & 31;
    const int wid  = tid >> 5;
    const int wm   = wid & 1;         // M offset 32*wm
    const int wn   = wid >> 1;        // 0..3 -> N offset 32*wn
    const int m0 = blockIdx.x * 64;
    const int n0 = blockIdx.y * 128;

    const __nv_bfloat16* aA0 = g_A0 + (size_t)m0 * KP2;
    const __nv_bfloat16* aA1 = g_A1 + (size_t)m0 * KP2;
    const __nv_bfloat16* bB0g = g_B0 + (size_t)n0 * KP2;
    const __nv_bfloat16* bB1g = g_B1 + (size_t)n0 * KP2;

    auto load_chunk = [&](int c) {
        uint32_t sbase = sb + (uint32_t)(c & 1) * STAGE_B;
        // A0 / A1 : 64 rows x 8 segs = 512 segs each
        #pragma unroll
        for (int tt = 0; tt < 2; tt++) {
            const __nv_bfloat16* gp = tt ? aA1 : aA0;
            #pragma unroll
            for (int it = 0; it < 2; it++) {
                int i = tid + it * 256;           // 0..511
                int row = i >> 3, seg = i & 7;
                uint32_t dst = sbase + (uint32_t)tt * A_TILE_B
                             + swz((uint32_t)row * 128 + (uint32_t)seg * 16);
                const void* src = gp + (size_t)row * KP2 + (size_t)c * 64 + seg * 8;
                asm volatile("cp.async.cg.shared.global [%0], [%1], 16;\n"
                             :: "r"(dst), "l"(src));
            }
        }
        // B0 / B1 : 128 rows x 8 segs = 1024 segs each
        #pragma unroll
        for (int tt = 0; tt < 2; tt++) {
            const __nv_bfloat16* gp = tt ? bB1g : bB0g;
            #pragma unroll
            for (int it = 0; it < 4; it++) {
                int i = tid + it * 256;           // 0..1023
                int row = i >> 3, seg = i & 7;
                uint32_t dst = sbase + 2 * A_TILE_B + (uint32_t)tt * B_TILE_B
                             + swz((uint32_t)row * 128 + (uint32_t)seg * 16);
                const void* src = gp + (size_t)row * KP2 + (size_t)c * 64 + seg * 8;
                asm volatile("cp.async.cg.shared.global [%0], [%1], 16;\n"
                             :: "r"(dst), "l"(src));
            }
        }
        asm volatile("cp.async.commit_group;\n" ::: "memory");
    };

    // fp32 accumulators: [mtile(16)][n8-tile(4 over 32N)][4]
    float acc[2][4][4];
    #pragma unroll
    for (int i = 0; i < 2; i++)
        #pragma unroll
        for (int jj = 0; jj < 4; jj++)
            #pragma unroll
            for (int k = 0; k < 4; k++) acc[i][jj][k] = 0.f;

    // ldmatrix per-lane address components (same fragment maps as R5, verified)
    const uint32_t a_row  = (uint32_t)(wm * 32 + (lane & 15));
    const uint32_t a_byte = (uint32_t)((lane >> 4) << 4);
    const uint32_t b_row  = (uint32_t)(wn * 32 + (lane & 7) + ((lane >> 4) << 3));
    const uint32_t b_byte = (uint32_t)((lane & 8) << 1);

    load_chunk(0);

    for (int c = 0; c < NC; c++) {
        if (c + 1 < NC) load_chunk(c + 1);
        if (c + 1 < NC) asm volatile("cp.async.wait_group 1;\n" ::: "memory");
        else            asm volatile("cp.async.wait_group 0;\n" ::: "memory");
        __syncthreads();

        const uint32_t stage = sb + (uint32_t)(c & 1) * STAGE_B;
        const uint32_t aB0 = stage;
        const uint32_t aB1 = stage + A_TILE_B;
        const uint32_t bB0 = stage + 2 * A_TILE_B;
        const uint32_t bB1 = stage + 2 * A_TILE_B + B_TILE_B;

        #pragma unroll
        for (int ks = 0; ks < 4; ks++) {
            const uint32_t kb = (uint32_t)ks * 32;
            uint32_t a0f[2][4], a1f[2][4];
            #pragma unroll
            for (int mt = 0; mt < 2; mt++) {
                uint32_t off = swz((a_row + mt * 16) * 128 + kb + a_byte);
                LDSM4(a0f[mt][0], a0f[mt][1], a0f[mt][2], a0f[mt][3], aB0 + off);
                LDSM4(a1f[mt][0], a1f[mt][1], a1f[mt][2], a1f[mt][3], aB1 + off);
            }
            uint32_t b0f[2][4], b1f[2][4];
            #pragma unroll
            for (int nt = 0; nt < 2; nt++) {
                uint32_t off = swz((b_row + nt * 16) * 128 + kb + b_byte);
                LDSM4(b0f[nt][0], b0f[nt][1], b0f[nt][2], b0f[nt][3], bB0 + off);
                LDSM4(b1f[nt][0], b1f[nt][1], b1f[nt][2], b1f[nt][3], bB1 + off);
            }
            #pragma unroll
            for (int mt = 0; mt < 2; mt++) {
                #pragma unroll
                for (int nt = 0; nt < 2; nt++) {
                    MMA16816(acc[mt][2 * nt],     a0f[mt], b0f[nt][0], b0f[nt][1]);
                    MMA16816(acc[mt][2 * nt + 1], a0f[mt], b0f[nt][2], b0f[nt][3]);
                    MMA16816(acc[mt][2 * nt],     a0f[mt], b1f[nt][0], b1f[nt][1]);
                    MMA16816(acc[mt][2 * nt + 1], a0f[mt], b1f[nt][2], b1f[nt][3]);
                    MMA16816(acc[mt][2 * nt],     a1f[mt], b0f[nt][0], b0f[nt][1]);
                    MMA16816(acc[mt][2 * nt + 1], a1f[mt], b0f[nt][2], b0f[nt][3]);
                }
            }
        }
        __syncthreads();
    }

    // epilogue: fragment thread t holds rows {t/4, t/4+8}, cols {2(t%4), +1}
    float2 bias[4];
    {
        const int nbase = n0 + wn * 32 + 2 * (lane & 3);
        #pragma unroll
        for (int nt8 = 0; nt8 < 4; nt8++) {
            bias[nt8].x = bih[nbase + nt8 * 8];
            bias[nt8].y = bih[nbase + nt8 * 8 + 1];
        }
    }
    #pragma unroll
    for (int mt = 0; mt < 2; mt++) {
        const int mlo = m0 + wm * 32 + mt * 16 + (lane >> 2);
        #pragma unroll
        for (int nt8 = 0; nt8 < 4; nt8++) {
            const int n = n0 + wn * 32 + nt8 * 8 + 2 * (lane & 3);
            float2 lo, hi;
            lo.x = acc[mt][nt8][0] + bias[nt8].x;
            lo.y = acc[mt][nt8][1] + bias[nt8].y;
            hi.x = acc[mt][nt8][2] + bias[nt8].x;
            hi.y = acc[mt][nt8][3] + bias[nt8].y;
            *(float2*)(g_gi + (size_t)mlo * NGI + n)       = lo;
            *(float2*)(g_gi + (size_t)(mlo + 8) * NGI + n) = hi;
        }
    }
}

// =====================================================================
// Kernel 4: persistent GRU (all 31 steps) + output head.
// 128 CTAs = 8 b-tiles(16) x 16 j-tiles(16). W_hh slice (48 KB) cached
// in smem ONCE; software grid barrier between steps; h via global with
// __ldcg (L1 is incoherent across SMs).
// =====================================================================
#define GRU_CTAS   128
#define WS_ROWLEN  260                          // 256 + pad (4-bank stride)
#define GRU_SMEM   ((3 * 16 * WS_ROWLEN + 16 * RNN_) * 4)   // 66304 B

__global__ __launch_bounds__(256, 1) void gru_persist(
    const float* __restrict__ Whh,   // (768,256)
    const float* __restrict__ bhh,   // (768)
    const float* __restrict__ Wout,  // (10,256)
    const float* __restrict__ bout,  // (10)
    float* __restrict__ out)         // (128,10)
{
    extern __shared__ float dsm[];
    float* ws = dsm;                        // [3*16][260]
    float* hs = dsm + 3 * 16 * WS_ROWLEN;   // [16][256]

    const int tid = threadIdx.x;
    const int bt = blockIdx.x >> 4, jt = blockIdx.x & 15;
    const int b0 = bt * 16, j0 = jt * 16;
    const int tx = tid & 15, ty = tid >> 4;

    // load W_hh slice once: rows (gg*256 + j0 + j), 256 cols
    for (int i = tid; i < 3072; i += 256) {          // 3072 float4
        int r = i >> 6;                              // 0..47 = gg*16 + j
        int c = (i & 63) * 4;
        const float* src = &Whh[((r >> 4) * RNN_ + j0 + (r & 15)) * RNN_ + c];
        float4 v = *(const float4*)src;
        float* d = ws + r * WS_ROWLEN + c;
        d[0] = v.x; d[1] = v.y; d[2] = v.z; d[3] = v.w;
    }

    const int j = j0 + tx;
    const int b = b0 + ty;
    const float br = bhh[j], bz = bhh[RNN_ + j], bn = bhh[2 * RNN_ + j];
    const float* w0 = ws + (0 * 16 + tx) * WS_ROWLEN;
    const float* w1 = ws + (1 * 16 + tx) * WS_ROWLEN;
    const float* w2 = ws + (2 * 16 + tx) * WS_ROWLEN;

    for (int t = 0; t < W_; t++) {
        // fill hs with h_{t-1} for this b-tile (zeros at t=0)
        if (t == 0) {
            #pragma unroll
            for (int i = tid; i < 16 * 64; i += 256)
                *(float4*)&hs[i * 4] = make_float4(0.f, 0.f, 0.f, 0.f);
        } else {
            const float* hi = g_h[t & 1];
            #pragma unroll
            for (int i = tid; i < 16 * 64; i += 256) {
                int r = i >> 6, c = (i & 63) * 4;
                float4 v = __ldcg((const float4*)&hi[(b0 + r) * RNN_ + c]);
                *(float4*)&hs[r * RNN_ + c] = v;
            }
        }
        __syncthreads();

        float a0 = 0.f, a1 = 0.f, a2 = 0.f;
        const float* hr_ = hs + ty * RNN_;
        #pragma unroll 8
        for (int k = 0; k < RNN_; k += 4) {
            float4 h4 = *(const float4*)&hr_[k];
            float4 x0 = *(const float4*)&w0[k];
            float4 x1 = *(const float4*)&w1[k];
            float4 x2 = *(const float4*)&w2[k];
            a0 += x0.x * h4.x + x0.y * h4.y + x0.z * h4.z + x0.w * h4.w;
            a1 += x1.x * h4.x + x1.y * h4.y + x1.z * h4.z + x1.w * h4.w;
            a2 += x2.x * h4.x + x2.y * h4.y + x2.z * h4.z + x2.w * h4.w;
        }

        const float* gi_t = g_gi + (size_t)t * B_ * NGI + (size_t)b * NGI;
        float ir  = gi_t[j];
        float iz  = gi_t[RNN_ + j];
        float inn = gi_t[2 * RNN_ + j];
        float r = 1.f / (1.f + expf(-(ir + a0 + br)));
        float z = 1.f / (1.f + expf(-(iz + a1 + bz)));
        float n = tanhf(inn + r * (a2 + bn));
        float hprev = hs[ty * RNN_ + j];
        g_h[(t + 1) & 1][b * RNN_ + j] = (1.f - z) * n + z * hprev;

        // ---- grid barrier (gen/count, release-acquire) ----
        __threadfence();
        __syncthreads();
        if (tid == 0) {
            unsigned gen = g_bar_gen;
            if (atomicAdd(&g_bar_cnt, 1u) == GRU_CTAS - 1) {
                g_bar_cnt = 0;
                __threadfence();
                g_bar_gen = gen + 1;
            } else {
                while (g_bar_gen == gen) __nanosleep(32);
            }
        }
        __syncthreads();
    }

    // output head: 8 CTAs (jt==0), 16 b-rows x 10 outputs each
    if (jt == 0) {
        const float* hf = g_h[W_ & 1];   // g_h[1]
        for (int i = tid; i < 16 * OUT_; i += 256) {
            int bb = b0 + i / OUT_, o = i % OUT_;
            float s = 0.f;
            #pragma unroll 8
            for (int k = 0; k < RNN_; k += 4) {
                float4 h4 = __ldcg((const float4*)&hf[bb * RNN_ + k]);
                float4 w4 = *(const float4*)&Wout[o * RNN_ + k];
                s += h4.x * w4.x + h4.y * w4.y + h4.z * w4.z + h4.w * w4.w;
            }
            out[bb * OUT_ + o] = 1.f / (1.f + expf(-(s + bout[o])));
        }
    }
}

// =====================================================================
extern "C" void kernel_launch(void* const* d_in, const int* in_sizes, int n_in,
                              void* d_out, int out_size)
{
    const float* x     = (const float*)d_in[0];
    const float* W_aug = (const float*)d_in[1];
    // d_in[2] = b_aug: constant, cancels in increments
    const float* W_ih  = (const float*)d_in[3];
    const float* W_hh  = (const float*)d_in[4];
    const float* b_ih  = (const float*)d_in[5];
    const float* b_hh  = (const float*)d_in[6];
    const float* W_out = (const float*)d_in[7];
    const float* b_out = (const float*)d_in[8];
    float* out = (float*)d_out;

    cudaFuncSetAttribute(gemm_mma, cudaFuncAttributeMaxDynamicSharedMemorySize, GEMM_SMEM);
    cudaFuncSetAttribute(gru_persist, cudaFuncAttributeMaxDynamicSharedMemorySize, GRU_SMEM);

    sig_kernel<<<dim3(W_, B_ * G_), 128>>>(x, W_aug);
    prep_w<<<(NGI * KP2 + 255) / 256, 256>>>(W_ih);
    gemm_mma<<<dim3(MROWS / 64, NGI / 128), 256, GEMM_SMEM>>>(b_ih);
    gru_persist<<<GRU_CTAS, 256, GRU_SMEM>>>(W_hh, b_hh, W_out, b_out, out);
}

// round 7
// speedup vs baseline: 2.7891x; 1.1738x over previous
#include <cuda_runtime.h>
#include <cuda_bf16.h>
#include <math.h>
#include <stdint.h>

// ---------------- problem constants ----------------
#define B_      128
#define STREAM_ 512
#define INCH    4
#define EXTRA_  5
#define G_      2
#define STEP_   16
#define SIGC    1110        // C + C^2 + C^3, C=10
#define W_      31          // windows
#define F_      2220        // GROUPS * SIGC
#define RNN_    256
#define OUT_    10
#define KP2     2240        // F_ padded to multiple of 64 (bf16 chunk)
#define MROWS   (W_ * B_)   // 3968
#define NGI     768         // 3 * RNN
#define NC      (KP2 / 64)  // 35 K-chunks of 64 bf16 (128 bytes)

// ---------------- device scratch (static, allowed) ----------------
__device__ __nv_bfloat16 g_A0[MROWS * KP2];   // sig hi  (~17.8 MB)
__device__ __nv_bfloat16 g_A1[MROWS * KP2];   // sig lo
__device__ __nv_bfloat16 g_B0[NGI * KP2];     // W_ih hi (~3.4 MB)
__device__ __nv_bfloat16 g_B1[NGI * KP2];     // W_ih lo
__device__ float g_gi[MROWS * NGI];           // ~12 MB
__device__ float g_h [2][B_ * RNN_];          // ping-pong hidden state

// grid barrier state (self-resetting; gen monotonic across graph replays)
__device__ volatile unsigned g_bar_gen;
__device__ unsigned g_bar_cnt;

// ---------------- PTX helpers (portable: sm_80/90 class only) ----------------
__device__ __forceinline__ uint32_t smem_u32(const void* p) {
    uint32_t a;
    asm("{ .reg .u64 t; cvta.to.shared.u64 t, %1; cvt.u32.u64 %0, t; }" : "=r"(a) : "l"(p));
    return a;
}

__device__ __forceinline__ uint32_t swz(uint32_t off) { return off ^ ((off >> 3) & 0x70); }

#define LDSM4(r0, r1, r2, r3, addr)                                               \
    asm volatile("ldmatrix.sync.aligned.m8n8.x4.shared.b16 {%0,%1,%2,%3}, [%4];"  \
        : "=r"(r0), "=r"(r1), "=r"(r2), "=r"(r3) : "r"(addr))

// D += A(16x16) * B(16x8), bf16 in, fp32 accum. row.col = both K-contiguous.
#define MMA16816(d, a, b0v, b1v)                                                  \
    asm volatile("mma.sync.aligned.m16n8k16.row.col.f32.bf16.bf16.f32 "           \
        "{%0,%1,%2,%3}, {%4,%5,%6,%7}, {%8,%9}, {%0,%1,%2,%3};"                   \
        : "+f"((d)[0]), "+f"((d)[1]), "+f"((d)[2]), "+f"((d)[3])                  \
        : "r"((a)[0]), "r"((a)[1]), "r"((a)[2]), "r"((a)[3]), "r"(b0v), "r"(b1v))

// split fp32 -> two bf16 (hi = rn(v), lo = rn(v - hi))
__device__ __forceinline__ void store_split(size_t idx, float v,
                                            __nv_bfloat16* a0, __nv_bfloat16* a1) {
    __nv_bfloat16 h = __float2bfloat16(v);
    a0[idx] = h;
    a1[idx] = __float2bfloat16(v - __bfloat162float(h));
}

// =====================================================================
// Kernel 1: path signatures (Chen, depth 3) -> split bf16 into g_A0/g_A1
// =====================================================================
__global__ __launch_bounds__(128) void sig_kernel(
    const float* __restrict__ x,       // (128,512,4)
    const float* __restrict__ W_aug)   // (2,5,4)
{
    const int w  = blockIdx.x;
    const int bg = blockIdx.y;
    const int b  = bg >> 1;
    const int g  = bg & 1;
    const int tid = threadIdx.x;

    __shared__ __align__(16) float xs[32][4];
    __shared__ __align__(16) float dxw[31][10];

    {
        int row = tid >> 2, ch = tid & 3;
        xs[row][ch] = x[(b * STREAM_ + w * STEP_ + row) * INCH + ch];
    }
    __syncthreads();

    for (int idx = tid; idx < 31 * 10; idx += 128) {
        int j = idx / 10, c = idx % 10;
        float v;
        if (c < 4) {
            v = xs[j + 1][c] - xs[j][c];
        } else if (c == 4) {
            v = 1.0f / 511.0f;
        } else {
            int e = c - 5;
            const float* wa = W_aug + (g * EXTRA_ + e) * INCH;
            v = 0.f;
            #pragma unroll
            for (int i = 0; i < 4; i++) v += wa[i] * (xs[j + 1][i] - xs[j][i]);
        }
        dxw[j][c] = v;
    }
    __syncthreads();

    const size_t base = (size_t)(w * B_ + b) * KP2 + (size_t)g * SIGC;

    if (tid < 100) {
        const int a  = tid / 10;
        const int bb = tid % 10;
        float s1a = 0.f, s2 = 0.f;
        float s3[10];
        #pragma unroll
        for (int c = 0; c < 10; c++) s3[c] = 0.f;

        for (int j = 0; j < 31; j++) {
            float dxa = dxw[j][a];
            float dxb = dxw[j][bb];
            float factor = s2 + dxb * (0.5f * s1a + (1.0f / 6.0f) * dxa);
            #pragma unroll
            for (int c = 0; c < 10; c++) s3[c] += factor * dxw[j][c];
            s2  += dxb * (s1a + 0.5f * dxa);
            s1a += dxa;
        }
        if (bb == 0) store_split(base + a, s1a, g_A0, g_A1);
        store_split(base + 10 + tid, s2, g_A0, g_A1);
        #pragma unroll
        for (int c = 0; c < 10; c++)
            store_split(base + 110 + tid * 10 + c, s3[c], g_A0, g_A1);
    }
    // zero K-pad columns (g==1 block handles it once per row)
    if (g == 1 && tid < (KP2 - F_)) {
        size_t idx = (size_t)(w * B_ + b) * KP2 + F_ + tid;
        g_A0[idx] = __float2bfloat16(0.f);
        g_A1[idx] = __float2bfloat16(0.f);
    }
}

// =====================================================================
// Kernel 2: split+pad W_ih (768 x 2220) into g_B0/g_B1 (768 x 2240)
// =====================================================================
__global__ __launch_bounds__(256) void prep_w(const float* __restrict__ Wih)
{
    int idx = blockIdx.x * 256 + threadIdx.x;
    if (idx < NGI * KP2) {
        int n = idx / KP2, k = idx - n * KP2;
        float v = (k < F_) ? Wih[n * F_ + k] : 0.f;
        store_split((size_t)idx, v, g_B0, g_B1);
    }
}

// =====================================================================
// Kernel 3: GI = sig @ W_ih^T + b_ih via mma.sync bf16-split (3 products).
// 64x128 CTA tile (372 tiles, 2 CTAs/SM), 8 warps of 32(M)x32(N),
// K-chunk 64, double-buffered cp.async, SW128 smem, ldmatrix TN.
// =====================================================================
#define A_TILE_B    8192                   // 64 rows x 128 bytes
#define B_TILE_B    16384                  // 128 rows x 128 bytes
#define STAGE_B     (2 * A_TILE_B + 2 * B_TILE_B)   // 49152
#define GEMM_SMEM   (2 * STAGE_B)          // 98304 bytes (2 stages)

__global__ __launch_bounds__(256, 2) void gemm_mma(const float* __restrict__ bih)
{
    extern __shared__ char smem[];
    const uint32_t sb = smem_u32(smem);
    const int tid  = threadIdx.x;
    const int lane = tid & 31;
    const int wid  = tid >> 5;
    const int wm   = wid & 1;         // M offset 32*wm
    const int wn   = wid >> 1;        // 0..3 -> N offset 32*wn
    const int m0 = blockIdx.x * 64;
    const int n0 = blockIdx.y * 128;

    const __nv_bfloat16* aA0 = g_A0 + (size_t)m0 * KP2;
    const __nv_bfloat16* aA1 = g_A1 + (size_t)m0 * KP2;
    const __nv_bfloat16* bB0g = g_B0 + (size_t)n0 * KP2;
    const __nv_bfloat16* bB1g = g_B1 + (size_t)n0 * KP2;

    auto load_chunk = [&](int c) {
        uint32_t sbase = sb + (uint32_t)(c & 1) * STAGE_B;
        #pragma unroll
        for (int tt = 0; tt < 2; tt++) {
            const __nv_bfloat16* gp = tt ? aA1 : aA0;
            #pragma unroll
            for (int it = 0; it < 2; it++) {
                int i = tid + it * 256;           // 0..511
                int row = i >> 3, seg = i & 7;
                uint32_t dst = sbase + (uint32_t)tt * A_TILE_B
                             + swz((uint32_t)row * 128 + (uint32_t)seg * 16);
                const void* src = gp + (size_t)row * KP2 + (size_t)c * 64 + seg * 8;
                asm volatile("cp.async.cg.shared.global [%0], [%1], 16;\n"
                             :: "r"(dst), "l"(src));
            }
        }
        #pragma unroll
        for (int tt = 0; tt < 2; tt++) {
            const __nv_bfloat16* gp = tt ? bB1g : bB0g;
            #pragma unroll
            for (int it = 0; it < 4; it++) {
                int i = tid + it * 256;           // 0..1023
                int row = i >> 3, seg = i & 7;
                uint32_t dst = sbase + 2 * A_TILE_B + (uint32_t)tt * B_TILE_B
                             + swz((uint32_t)row * 128 + (uint32_t)seg * 16);
                const void* src = gp + (size_t)row * KP2 + (size_t)c * 64 + seg * 8;
                asm volatile("cp.async.cg.shared.global [%0], [%1], 16;\n"
                             :: "r"(dst), "l"(src));
            }
        }
        asm volatile("cp.async.commit_group;\n" ::: "memory");
    };

    float acc[2][4][4];
    #pragma unroll
    for (int i = 0; i < 2; i++)
        #pragma unroll
        for (int jj = 0; jj < 4; jj++)
            #pragma unroll
            for (int k = 0; k < 4; k++) acc[i][jj][k] = 0.f;

    const uint32_t a_row  = (uint32_t)(wm * 32 + (lane & 15));
    const uint32_t a_byte = (uint32_t)((lane >> 4) << 4);
    const uint32_t b_row  = (uint32_t)(wn * 32 + (lane & 7) + ((lane >> 4) << 3));
    const uint32_t b_byte = (uint32_t)((lane & 8) << 1);

    load_chunk(0);

    for (int c = 0; c < NC; c++) {
        if (c + 1 < NC) load_chunk(c + 1);
        if (c + 1 < NC) asm volatile("cp.async.wait_group 1;\n" ::: "memory");
        else            asm volatile("cp.async.wait_group 0;\n" ::: "memory");
        __syncthreads();

        const uint32_t stage = sb + (uint32_t)(c & 1) * STAGE_B;
        const uint32_t aB0 = stage;
        const uint32_t aB1 = stage + A_TILE_B;
        const uint32_t bB0 = stage + 2 * A_TILE_B;
        const uint32_t bB1 = stage + 2 * A_TILE_B + B_TILE_B;

        #pragma unroll
        for (int ks = 0; ks < 4; ks++) {
            const uint32_t kb = (uint32_t)ks * 32;
            uint32_t a0f[2][4], a1f[2][4];
            #pragma unroll
            for (int mt = 0; mt < 2; mt++) {
                uint32_t off = swz((a_row + mt * 16) * 128 + kb + a_byte);
                LDSM4(a0f[mt][0], a0f[mt][1], a0f[mt][2], a0f[mt][3], aB0 + off);
                LDSM4(a1f[mt][0], a1f[mt][1], a1f[mt][2], a1f[mt][3], aB1 + off);
            }
            uint32_t b0f[2][4], b1f[2][4];
            #pragma unroll
            for (int nt = 0; nt < 2; nt++) {
                uint32_t off = swz((b_row + nt * 16) * 128 + kb + b_byte);
                LDSM4(b0f[nt][0], b0f[nt][1], b0f[nt][2], b0f[nt][3], bB0 + off);
                LDSM4(b1f[nt][0], b1f[nt][1], b1f[nt][2], b1f[nt][3], bB1 + off);
            }
            #pragma unroll
            for (int mt = 0; mt < 2; mt++) {
                #pragma unroll
                for (int nt = 0; nt < 2; nt++) {
                    MMA16816(acc[mt][2 * nt],     a0f[mt], b0f[nt][0], b0f[nt][1]);
                    MMA16816(acc[mt][2 * nt + 1], a0f[mt], b0f[nt][2], b0f[nt][3]);
                    MMA16816(acc[mt][2 * nt],     a0f[mt], b1f[nt][0], b1f[nt][1]);
                    MMA16816(acc[mt][2 * nt + 1], a0f[mt], b1f[nt][2], b1f[nt][3]);
                    MMA16816(acc[mt][2 * nt],     a1f[mt], b0f[nt][0], b0f[nt][1]);
                    MMA16816(acc[mt][2 * nt + 1], a1f[mt], b0f[nt][2], b0f[nt][3]);
                }
            }
        }
        __syncthreads();
    }

    float2 bias[4];
    {
        const int nbase = n0 + wn * 32 + 2 * (lane & 3);
        #pragma unroll
        for (int nt8 = 0; nt8 < 4; nt8++) {
            bias[nt8].x = bih[nbase + nt8 * 8];
            bias[nt8].y = bih[nbase + nt8 * 8 + 1];
        }
    }
    #pragma unroll
    for (int mt = 0; mt < 2; mt++) {
        const int mlo = m0 + wm * 32 + mt * 16 + (lane >> 2);
        #pragma unroll
        for (int nt8 = 0; nt8 < 4; nt8++) {
            const int n = n0 + wn * 32 + nt8 * 8 + 2 * (lane & 3);
            float2 lo, hi;
            lo.x = acc[mt][nt8][0] + bias[nt8].x;
            lo.y = acc[mt][nt8][1] + bias[nt8].y;
            hi.x = acc[mt][nt8][2] + bias[nt8].x;
            hi.y = acc[mt][nt8][3] + bias[nt8].y;
            *(float2*)(g_gi + (size_t)mlo * NGI + n)       = lo;
            *(float2*)(g_gi + (size_t)(mlo + 8) * NGI + n) = hi;
        }
    }
}

// =====================================================================
// Kernel 4: persistent GRU v2 (W_hh in REGISTERS) + output head.
// 128 CTAs = 8 b-tiles(16) x 16 j-tiles(16), 256 threads.
// Lane (warp w, jj=lane>>4, kc=lane&15) owns j = j0+2w+jj, k-slice
// kc*16..+15: W_hh[3][16] lives in 48 registers for all 31 steps.
// Per step: conflict-free LDS of h only (smem layout [b][i4][kc][4]),
// 768 FMA, then 45-SHFL transpose-butterfly reduce over the 16
// kc-lanes landing b=kc's three gate sums on lane kc.
// =====================================================================
#define GRU_CTAS   128

__global__ __launch_bounds__(256, 1) void gru_persist(
    const float* __restrict__ Whh,   // (768,256)
    const float* __restrict__ bhh,   // (768)
    const float* __restrict__ Wout,  // (10,256)
    const float* __restrict__ bout,  // (10)
    float* __restrict__ out)         // (128,10)
{
    // hs[b][i4][kc][4] : element k of row b at ((b*4 + (k>>2)&3)*16 + k>>4)*4 + (k&3)
    __shared__ __align__(16) float hs[4096];   // 16 KB

    const int tid  = threadIdx.x;
    const int w    = tid >> 5;
    const int lane = tid & 31;
    const int jj   = lane >> 4;
    const int kc   = lane & 15;
    const int bt = blockIdx.x >> 4, jt = blockIdx.x & 15;
    const int b0 = bt * 16, j0 = jt * 16;
    const int j  = j0 + (w << 1) + jj;   // this lane's gate column
    const int b  = b0 + kc;              // this lane's output batch row

    // ---- one-time: W_hh[3 gates][my 16-k slice] -> registers ----
    float4 W4[3][4];
    #pragma unroll
    for (int g = 0; g < 3; g++)
        #pragma unroll
        for (int i4 = 0; i4 < 4; i4++)
            W4[g][i4] = *(const float4*)&Whh[(g * RNN_ + j) * RNN_ + kc * 16 + i4 * 4];

    const float br = bhh[j], bz = bhh[RNN_ + j], bn = bhh[2 * RNN_ + j];
    // h_prev smem index for (b=kc row, col j)
    const int hprev_idx = ((kc * 4 + ((j >> 2) & 3)) * 16 + (j >> 4)) * 4 + (j & 3);

    for (int t = 0; t < W_; t++) {
        // ---- fill hs (swizzled) ----
        if (t == 0) {
            #pragma unroll
            for (int i = tid; i < 1024; i += 256)
                *(float4*)&hs[i * 4] = make_float4(0.f, 0.f, 0.f, 0.f);
        } else {
            const float* hi = g_h[t & 1];
            #pragma unroll
            for (int i = tid; i < 1024; i += 256) {
                int bb = i >> 6, q = i & 63;         // q = k/4
                int kcs = q >> 2, i4 = q & 3;
                float4 v = __ldcg((const float4*)&hi[(b0 + bb) * RNN_ + q * 4]);
                *(float4*)&hs[((bb * 4 + i4) * 16 + kcs) * 4] = v;
            }
        }
        __syncthreads();

        // prefetch gi for this lane's output (consumed after reduction)
        const float* gi_t = g_gi + (size_t)t * (B_ * NGI) + (size_t)b * NGI;
        float ir  = __ldcg(&gi_t[j]);
        float iz  = __ldcg(&gi_t[RNN_ + j]);
        float inn = __ldcg(&gi_t[2 * RNN_ + j]);

        // ---- partials: all 16 b-rows over my 16-k slice ----
        float acc[16][3];
        #pragma unroll
        for (int bb = 0; bb < 16; bb++) {
            float4 h0 = *(const float4*)&hs[((bb * 4 + 0) * 16 + kc) * 4];
            float4 h1 = *(const float4*)&hs[((bb * 4 + 1) * 16 + kc) * 4];
            float4 h2 = *(const float4*)&hs[((bb * 4 + 2) * 16 + kc) * 4];
            float4 h3 = *(const float4*)&hs[((bb * 4 + 3) * 16 + kc) * 4];
            #pragma unroll
            for (int g = 0; g < 3; g++) {
                float s;
                s  = W4[g][0].x * h0.x + W4[g][0].y * h0.y + W4[g][0].z * h0.z + W4[g][0].w * h0.w;
                s += W4[g][1].x * h1.x + W4[g][1].y * h1.y + W4[g][1].z * h1.z + W4[g][1].w * h1.w;
                s += W4[g][2].x * h2.x + W4[g][2].y * h2.y + W4[g][2].z * h2.z + W4[g][2].w * h2.w;
                s += W4[g][3].x * h3.x + W4[g][3].y * h3.y + W4[g][3].z * h3.z + W4[g][3].w * h3.w;
                acc[bb][g] = s;
            }
        }

        // ---- transpose-butterfly reduce over 16 kc-lanes (45 SHFL) ----
        // invariant: after mask m, acc[bb] holds b_local = bb | (kc & ~(2m-1) bits);
        // final acc[0][g] = full sum for b_local = kc.
        #pragma unroll
        for (int m = 8; m >= 1; m >>= 1) {
            #pragma unroll
            for (int bb = 0; bb < m; bb++) {
                #pragma unroll
                for (int g = 0; g < 3; g++) {
                    float lo = acc[bb][g], hi2 = acc[bb + m][g];
                    float send = (kc & m) ? lo  : hi2;
                    float keep = (kc & m) ? hi2 : lo;
                    acc[bb][g] = keep + __shfl_xor_sync(0xffffffffu, send, m);
                }
            }
        }

        // ---- gates for (b, j) ----
        float r = 1.f / (1.f + expf(-(ir + acc[0][0] + br)));
        float z = 1.f / (1.f + expf(-(iz + acc[0][1] + bz)));
        float n = tanhf(inn + r * (acc[0][2] + bn));
        float hprev = hs[hprev_idx];
        g_h[(t + 1) & 1][b * RNN_ + j] = (1.f - z) * n + z * hprev;

        // ---- grid barrier ----
        __threadfence();
        __syncthreads();
        if (tid == 0) {
            unsigned gen = g_bar_gen;
            if (atomicAdd(&g_bar_cnt, 1u) == GRU_CTAS - 1) {
                g_bar_cnt = 0;
                __threadfence();
                g_bar_gen = gen + 1;
            } else {
                while (g_bar_gen == gen) __nanosleep(32);
            }
        }
        __syncthreads();
    }

    // ---- output head: 8 CTAs (jt==0), 16 b-rows x 10 outputs each ----
    if (jt == 0) {
        const float* hf = g_h[W_ & 1];   // g_h[1]
        for (int i = tid; i < 16 * OUT_; i += 256) {
            int bb = b0 + i / OUT_, o = i % OUT_;
            float s = 0.f;
            #pragma unroll 8
            for (int k = 0; k < RNN_; k += 4) {
                float4 h4 = __ldcg((const float4*)&hf[bb * RNN_ + k]);
                float4 w4 = *(const float4*)&Wout[o * RNN_ + k];
                s += h4.x * w4.x + h4.y * w4.y + h4.z * w4.z + h4.w * w4.w;
            }
            out[bb * OUT_ + o] = 1.f / (1.f + expf(-(s + bout[o])));
        }
    }
}

// =====================================================================
extern "C" void kernel_launch(void* const* d_in, const int* in_sizes, int n_in,
                              void* d_out, int out_size)
{
    const float* x     = (const float*)d_in[0];
    const float* W_aug = (const float*)d_in[1];
    // d_in[2] = b_aug: constant, cancels in increments
    const float* W_ih  = (const float*)d_in[3];
    const float* W_hh  = (const float*)d_in[4];
    const float* b_ih  = (const float*)d_in[5];
    const float* b_hh  = (const float*)d_in[6];
    const float* W_out = (const float*)d_in[7];
    const float* b_out = (const float*)d_in[8];
    float* out = (float*)d_out;

    cudaFuncSetAttribute(gemm_mma, cudaFuncAttributeMaxDynamicSharedMemorySize, GEMM_SMEM);

    sig_kernel<<<dim3(W_, B_ * G_), 128>>>(x, W_aug);
    prep_w<<<(NGI * KP2 + 255) / 256, 256>>>(W_ih);
    gemm_mma<<<dim3(MROWS / 64, NGI / 128), 256, GEMM_SMEM>>>(b_ih);
    gru_persist<<<GRU_CTAS, 256>>>(W_hh, b_hh, W_out, b_out, out);
}